// round 14
// baseline (speedup 1.0000x reference)
#include <cuda_runtime.h>
#include <cuda_fp16.h>
#include <cstdint>

#define H       1024
#define BATCH   16384
#define BM      128
#define BN      128
#define BK      64
#define NT      (H / BK)            // 16
#define KC      8                   // 16B k-chunks per stage (64 halves)
#define PLANE   2064                // padded kc-plane stride (129*16B)
#define TILE_BYTES (KC * PLANE)     // 16512
#define STG_BYTES  (2 * TILE_BYTES) // 33024 (A + B)
#define STAGES  3
#define SMEM_TOTAL (STAGES * STG_BYTES)   // 99072 -> 2 CTAs/SM
#define MTILES  (BATCH / BM)        // 128
#define NTILES  (H / BN)            // 8
#define TILES_PER_PHASE (MTILES * NTILES) // 1024

// scratch (__device__ globals: allowed)
__device__ __half g_prevh[(size_t)BATCH * H];  // prev in fp16 (32MB)
__device__ __half g_th[(size_t)BATCH * H];     // t intermediate fp16 (32MB)
__device__ __half g_Wh[(size_t)H * H];         // Wur[:,H:2H]^T fp16
__device__ __half g_Uh[(size_t)H * H];         // U^T fp16
__device__ unsigned g_queue;
__device__ unsigned g_done[MTILES];

static __device__ __forceinline__ uint32_t smem_u32(const void* p) {
    return (uint32_t)__cvta_generic_to_shared(p);
}
static __device__ __forceinline__ void cp16(uint32_t dst, const void* src) {
    asm volatile("cp.async.cg.shared.global [%0], [%1], 16;" :: "r"(dst), "l"(src));
}
#define CP_COMMIT() asm volatile("cp.async.commit_group;" ::: "memory")
#define CP_WAIT(n)  asm volatile("cp.async.wait_group %0;" :: "n"(n) : "memory")

static __device__ __forceinline__ void ldsm_x4(uint32_t* r, uint32_t a) {
    asm volatile("ldmatrix.sync.aligned.m8n8.x4.shared.b16 {%0,%1,%2,%3}, [%4];"
                 : "=r"(r[0]), "=r"(r[1]), "=r"(r[2]), "=r"(r[3]) : "r"(a));
}
static __device__ __forceinline__ void mma_f16(float* c, const uint32_t* a, const uint32_t* b) {
    asm volatile("mma.sync.aligned.m16n8k16.row.col.f32.f16.f16.f32 "
                 "{%0,%1,%2,%3}, {%4,%5,%6,%7}, {%8,%9}, {%0,%1,%2,%3};"
                 : "+f"(c[0]), "+f"(c[1]), "+f"(c[2]), "+f"(c[3])
                 : "r"(a[0]), "r"(a[1]), "r"(a[2]), "r"(a[3]), "r"(b[0]), "r"(b[1]));
}

// ---------------------------------------------------------------------------
// stage loader: A [128 x 64] + B [128 x 64] fp16, layout [kc][row][16B],
// plane stride PLANE (padded: write-conflict <= 4-way, read conflict-free).
// Global: 8 consecutive threads cover one 128B row (fully coalesced).
// ---------------------------------------------------------------------------
static __device__ __forceinline__ void load_stage(uint32_t stageBase,
        const __half* __restrict__ Ag, int m0,
        const __half* __restrict__ Bg, int n0, int k0, int tid)
{
#pragma unroll
    for (int j = 0; j < 4; j++) {
        int idx = tid + j * 256;
        int r = idx >> 3, kc = idx & 7;
        cp16(stageBase + (uint32_t)kc * PLANE + (uint32_t)r * 16,
             Ag + (size_t)(m0 + r) * H + k0 + kc * 8);
    }
#pragma unroll
    for (int j = 0; j < 4; j++) {
        int idx = tid + j * 256;
        int r = idx >> 3, kc = idx & 7;
        cp16(stageBase + TILE_BYTES + (uint32_t)kc * PLANE + (uint32_t)r * 16,
             Bg + (size_t)(n0 + r) * H + k0 + kc * 8);
    }
}

// ---------------------------------------------------------------------------
// GEMM core: acc[4][4][4] += A[128x1024] @ B[1024x128]^T  (fp16 ops, f32 acc)
// 8 warps 2(M) x 4(N); warp tile 64x32; m16n8k16 HMMA.
// ---------------------------------------------------------------------------
static __device__ __forceinline__ void gemm_core(float acc[4][4][4],
        const __half* __restrict__ Ag, const __half* __restrict__ Bg,
        int m0, int n0, char* smem)
{
    const uint32_t sb = smem_u32(smem);
    const int tid  = threadIdx.x;
    const int lane = tid & 31;
    const int warp = tid >> 5;
    const int wr   = warp >> 2;   // 0..1 (M)
    const int wc   = warp & 3;    // 0..3 (N)

    // A: lanes0-7 m0-7/kc, 8-15 m8-15/kc, 16-23 m0-7/kc+1, 24-31 m8-15/kc+1
    const uint32_t a_off = (uint32_t)(lane >> 4) * PLANE
                         + (uint32_t)(wr * 64 + (lane & 15)) * 16;
    // B: lanes0-7 n0-7/kc, 8-15 n0-7/kc+1, 16-23 n8-15/kc, 24-31 n8-15/kc+1
    const uint32_t b_off = (uint32_t)((lane >> 3) & 1) * PLANE
                         + (uint32_t)(wc * 32 + ((lane >> 4) << 3) + (lane & 7)) * 16;

#pragma unroll
    for (int i = 0; i < 4; i++)
#pragma unroll
        for (int j = 0; j < 4; j++)
#pragma unroll
            for (int k = 0; k < 4; k++) acc[i][j][k] = 0.f;

    load_stage(sb, Ag, m0, Bg, n0, 0, tid);
    CP_COMMIT();
    load_stage(sb + STG_BYTES, Ag, m0, Bg, n0, BK, tid);
    CP_COMMIT();

    for (int i = 0; i < NT; ++i) {
        const int s = i % STAGES;
        if (i == NT - 1) CP_WAIT(0); else CP_WAIT(1);
        __syncthreads();

        const uint32_t Abase = sb + s * STG_BYTES;
        const uint32_t Bbase = Abase + TILE_BYTES;
#pragma unroll
        for (int ks = 0; ks < 4; ks++) {       // k16 steps within BK=64
            uint32_t af[4][4], bf[4][2];
#pragma unroll
            for (int mi = 0; mi < 4; mi++)
                ldsm_x4(af[mi], Abase + (uint32_t)(2 * ks) * PLANE + a_off
                                + (uint32_t)(mi * 16) * 16);
#pragma unroll
            for (int g = 0; g < 2; g++) {
                uint32_t tmp[4];
                ldsm_x4(tmp, Bbase + (uint32_t)(2 * ks) * PLANE + b_off
                             + (uint32_t)(g * 16) * 16);
                bf[2 * g][0] = tmp[0]; bf[2 * g][1] = tmp[1];
                bf[2 * g + 1][0] = tmp[2]; bf[2 * g + 1][1] = tmp[3];
            }
#pragma unroll
            for (int mi = 0; mi < 4; mi++)
#pragma unroll
                for (int ni = 0; ni < 4; ni++)
                    mma_f16(acc[mi][ni], af[mi], bf[ni]);
        }

        if (i + 2 < NT) {
            load_stage(sb + ((i + 2) % STAGES) * STG_BYTES,
                       Ag, m0, Bg, n0, (i + 2) * BK, tid);
            CP_COMMIT();
        }
    }
    __syncthreads();   // smem reuse safe for next tile
}

// ---------------------------------------------------------------------------
// prev -> fp16
// ---------------------------------------------------------------------------
__global__ __launch_bounds__(256) void ggru_convert(const float* __restrict__ prev) {
    size_t i = (size_t)blockIdx.x * 256 + threadIdx.x;   // one float4 each
    float4 v = reinterpret_cast<const float4*>(prev)[i];
    __half2 h0 = __floats2half2_rn(v.x, v.y);
    __half2 h1 = __floats2half2_rn(v.z, v.w);
    uint2 u;
    u.x = *reinterpret_cast<uint32_t*>(&h0);
    u.y = *reinterpret_cast<uint32_t*>(&h1);
    reinterpret_cast<uint2*>(g_prevh)[i] = u;
}

// ---------------------------------------------------------------------------
// transpose weights -> fp16 [n][k]; zero work-queue state
// ---------------------------------------------------------------------------
__global__ __launch_bounds__(256) void ggru_transpose(
    const float* __restrict__ Wur, const float* __restrict__ U)
{
    if (blockIdx.x == 0 && blockIdx.y == 0 && blockIdx.z == 0) {
        if (threadIdx.x < MTILES) g_done[threadIdx.x] = 0;
        if (threadIdx.x == 255) g_queue = 0;
    }
    __shared__ float tile[32][33];
    const int mat = blockIdx.z;
    const float* src = mat ? U : (Wur + H);
    const int lds = mat ? H : 2 * H;
    __half* dst = mat ? g_Uh : g_Wh;
    const int kBase = blockIdx.y * 32, nBase = blockIdx.x * 32;
    const int tx = threadIdx.x & 31, ty = threadIdx.x >> 5;

#pragma unroll
    for (int j = 0; j < 4; j++)
        tile[ty + j * 8][tx] = src[(size_t)(kBase + ty + j * 8) * lds + nBase + tx];
    __syncthreads();
#pragma unroll
    for (int j = 0; j < 4; j++)
        dst[(size_t)(nBase + ty + j * 8) * H + kBase + tx] = __float2half(tile[tx][ty + j * 8]);
}

// ---------------------------------------------------------------------------
// Fused persistent kernel: ids 0..1023 GEMM1, 1024..2047 GEMM2 (waits g_done)
// ---------------------------------------------------------------------------
__global__ __launch_bounds__(256, 2) void ggru_fused(
    const float* __restrict__ prev, const float* __restrict__ inp,
    const float* __restrict__ mask, float* __restrict__ out)
{
    extern __shared__ __align__(1024) char smem[];
    __shared__ unsigned s_claim;

    const int tid  = threadIdx.x;
    const int lane = tid & 31, warp = tid >> 5;
    const int wr = warp >> 2, wc = warp & 3;

    for (;;) {
        if (tid == 0) s_claim = atomicAdd(&g_queue, 1u);
        __syncthreads();
        const unsigned c = s_claim;
        __syncthreads();
        if (c >= 2u * TILES_PER_PHASE) return;

        if (c < TILES_PER_PHASE) {
            // ---------------- GEMM1: t = s * sigmoid(prev@Wr + g) ----------
            const int mb = (int)(c >> 3), nb = (int)(c & 7);
            const int m0 = mb * BM, n0 = nb * BN;
            float acc[4][4][4];
            gemm_core(acc, g_prevh, g_Wh, m0, n0, smem);

#pragma unroll
            for (int mi = 0; mi < 4; mi++) {
#pragma unroll
                for (int ni = 0; ni < 4; ni++) {
                    const int r0 = m0 + wr * 64 + mi * 16 + (lane >> 2);
                    const int c0 = n0 + wc * 32 + ni * 8 + (lane & 3) * 2;
#pragma unroll
                    for (int j = 0; j < 2; j++) {
                        const int row = r0 + j * 8;
                        const float* irow = inp + (size_t)row * (3 * H);
                        float2 g = *reinterpret_cast<const float2*>(irow + 2 * H + c0);
                        float2 s = *reinterpret_cast<const float2*>(irow + c0);
                        float x0 = acc[mi][ni][j * 2 + 0] + g.x;
                        float x1 = acc[mi][ni][j * 2 + 1] + g.y;
                        float t0 = s.x * (1.f / (1.f + __expf(-x0)));
                        float t1 = s.y * (1.f / (1.f + __expf(-x1)));
                        __half2 hv = __floats2half2_rn(t0, t1);
                        *reinterpret_cast<uint32_t*>(&g_th[(size_t)row * H + c0]) =
                            *reinterpret_cast<uint32_t*>(&hv);
                    }
                }
            }
            __threadfence();
            __syncthreads();
            if (tid == 0) atomicAdd(&g_done[mb], 1u);
        } else {
            // ---------------- GEMM2: out = prev + m*(tanh(t@U + s)+1) ------
            const unsigned id = c - TILES_PER_PHASE;
            const int mb = (int)(id >> 3), nb = (int)(id & 7);
            const int m0 = mb * BM, n0 = nb * BN;

            if (tid == 0) {
                while (atomicAdd(&g_done[mb], 0u) < (unsigned)NTILES) __nanosleep(64);
            }
            __syncthreads();
            __threadfence();

            float acc[4][4][4];
            gemm_core(acc, g_th, g_Uh, m0, n0, smem);

#pragma unroll
            for (int mi = 0; mi < 4; mi++) {
#pragma unroll
                for (int ni = 0; ni < 4; ni++) {
                    const int r0 = m0 + wr * 64 + mi * 16 + (lane >> 2);
                    const int c0 = n0 + wc * 32 + ni * 8 + (lane & 3) * 2;
#pragma unroll
                    for (int j = 0; j < 2; j++) {
                        const int row = r0 + j * 8;
                        float2 s  = *reinterpret_cast<const float2*>(inp + (size_t)row * (3 * H) + c0);
                        float2 pv = *reinterpret_cast<const float2*>(prev + (size_t)row * H + c0);
                        float mk = mask[row];
                        float n0v = tanhf(acc[mi][ni][j * 2 + 0] + s.x);
                        float n1v = tanhf(acc[mi][ni][j * 2 + 1] + s.y);
                        float2 o;
                        o.x = pv.x + mk * (n0v + 1.f);
                        o.y = pv.y + mk * (n1v + 1.f);
                        *reinterpret_cast<float2*>(out + (size_t)row * H + c0) = o;
                    }
                }
            }
        }
    }
}

// ---------------------------------------------------------------------------
extern "C" void kernel_launch(void* const* d_in, const int* in_sizes, int n_in,
                              void* d_out, int out_size) {
    const float* inp  = (const float*)d_in[0];   // [16384, 3072]
    const float* prev = (const float*)d_in[1];   // [16384, 1024]
    const float* mask = (const float*)d_in[2];   // [16384]
    const float* Wur  = (const float*)d_in[3];   // [1024, 2048]
    const float* U    = (const float*)d_in[4];   // [1024, 1024]
    float* out = (float*)d_out;                  // [16384, 1024]

    cudaFuncSetAttribute(ggru_fused, cudaFuncAttributeMaxDynamicSharedMemorySize, SMEM_TOTAL);

    ggru_convert<<<BATCH * H / (256 * 4), 256>>>(prev);
    ggru_transpose<<<dim3(32, 32, 2), 256>>>(Wur, U);
    ggru_fused<<<304, 256, SMEM_TOTAL>>>(prev, inp, mask, out);
}

// round 16
// speedup vs baseline: 1.8005x; 1.8005x over previous
#include <cuda_runtime.h>
#include <cuda_fp16.h>
#include <cstdint>

#define H       1024
#define BATCH   16384
#define BM      128
#define BN      128
#define BK      64                  // halves per k-stage (128B rows)
#define NT      (H / BK)            // 16
#define TILE_BYTES (BM * 128)       // 16KB
#define STG_BYTES  (2 * TILE_BYTES) // 32KB (A + B)
#define STAGES  3
#define SMEM_TOTAL (STAGES * STG_BYTES)   // 96KB -> 2 CTAs/SM
#define MTILES  (BATCH / BM)        // 128
#define NTILES  (H / BN)            // 8
#define TILES_PER_PHASE (MTILES * NTILES) // 1024

// scratch (__device__ globals: allowed)
__device__ __half g_prevh[(size_t)BATCH * H];  // prev in fp16 (32MB)
__device__ __half g_th[(size_t)BATCH * H];     // t intermediate fp16 (32MB)
__device__ __half g_Wh[(size_t)H * H];         // Wur[:,H:2H]^T fp16
__device__ __half g_Uh[(size_t)H * H];         // U^T fp16
__device__ unsigned g_queue;
__device__ unsigned g_done[MTILES];

static __device__ __forceinline__ uint32_t smem_u32(const void* p) {
    return (uint32_t)__cvta_generic_to_shared(p);
}
static __device__ __forceinline__ void cp16(uint32_t dst, const void* src) {
    asm volatile("cp.async.cg.shared.global [%0], [%1], 16;" :: "r"(dst), "l"(src));
}
#define CP_COMMIT() asm volatile("cp.async.commit_group;" ::: "memory")
#define CP_WAIT(n)  asm volatile("cp.async.wait_group %0;" :: "n"(n) : "memory")

static __device__ __forceinline__ void ldsm_x4(uint32_t* r, uint32_t a) {
    asm volatile("ldmatrix.sync.aligned.m8n8.x4.shared.b16 {%0,%1,%2,%3}, [%4];"
                 : "=r"(r[0]), "=r"(r[1]), "=r"(r[2]), "=r"(r[3]) : "r"(a));
}
static __device__ __forceinline__ void mma_f16(float* c, const uint32_t* a, const uint32_t* b) {
    asm volatile("mma.sync.aligned.m16n8k16.row.col.f32.f16.f16.f32 "
                 "{%0,%1,%2,%3}, {%4,%5,%6,%7}, {%8,%9}, {%0,%1,%2,%3};"
                 : "+f"(c[0]), "+f"(c[1]), "+f"(c[2]), "+f"(c[3])
                 : "r"(a[0]), "r"(a[1]), "r"(a[2]), "r"(a[3]), "r"(b[0]), "r"(b[1]));
}

// ---------------------------------------------------------------------------
// stage loader: A [128 x 64h] + B [128 x 64h] fp16, 128B rows, SW128 swizzle
// (conflict-free STS and LDSM — the layout validated in rounds 8/12).
// ---------------------------------------------------------------------------
static __device__ __forceinline__ void load_stage(uint32_t stageBase,
        const __half* __restrict__ Ag, int m0,
        const __half* __restrict__ Bg, int n0, int k0, int tid)
{
#pragma unroll
    for (int j = 0; j < 4; j++) {
        int idx = tid + j * 256;
        int r = idx >> 3, c = idx & 7;
        uint32_t off = (uint32_t)idx * 16;
        uint32_t sw = off ^ ((off >> 3) & 0x70);
        cp16(stageBase + sw, Ag + (size_t)(m0 + r) * H + k0 + c * 8);
    }
#pragma unroll
    for (int j = 0; j < 4; j++) {
        int idx = tid + j * 256;
        int r = idx >> 3, c = idx & 7;
        uint32_t off = (uint32_t)idx * 16;
        uint32_t sw = off ^ ((off >> 3) & 0x70);
        cp16(stageBase + TILE_BYTES + sw, Bg + (size_t)(n0 + r) * H + k0 + c * 8);
    }
}

// ---------------------------------------------------------------------------
// GEMM core: acc[4][4][4] += A[128x1024] @ B[1024x128]^T  (fp16 ops, f32 acc)
// 8 warps 2(M) x 4(N); warp tile 64x32; m16n8k16 HMMA fed by ldmatrix.x4.
// ---------------------------------------------------------------------------
static __device__ __forceinline__ void gemm_core(float acc[4][4][4],
        const __half* __restrict__ Ag, const __half* __restrict__ Bg,
        int m0, int n0, char* smem)
{
    const uint32_t sb = smem_u32(smem);
    const int tid  = threadIdx.x;
    const int lane = tid & 31;
    const int warp = tid >> 5;
    const int wr   = warp >> 2;   // 0..1 (M)
    const int wc   = warp & 3;    // 0..3 (N)

    // A: matrices (m0-7,k0-7)(m8-15,k0-7)(m0-7,k8-15)(m8-15,k8-15)
    const int a_r  = wr * 64 + (lane & 15);          // + mi*16
    const int a_cx = lane >> 4;                      // k-half chunk
    const int arx  = a_r & 7;                        // swizzle XOR (mi*16 invariant)
    // B: matrices (n0-7,k0-7)(n0-7,k8-15)(n8-15,k0-7)(n8-15,k8-15)
    const int b_r  = wc * 32 + ((lane >> 4) << 3) + (lane & 7);   // + g*16
    const int b_cx = (lane >> 3) & 1;
    const int brx  = b_r & 7;

#pragma unroll
    for (int i = 0; i < 4; i++)
#pragma unroll
        for (int j = 0; j < 4; j++)
#pragma unroll
            for (int k = 0; k < 4; k++) acc[i][j][k] = 0.f;

    load_stage(sb, Ag, m0, Bg, n0, 0, tid);
    CP_COMMIT();
    load_stage(sb + STG_BYTES, Ag, m0, Bg, n0, BK, tid);
    CP_COMMIT();

    for (int i = 0; i < NT; ++i) {
        const int s = i % STAGES;
        if (i == NT - 1) CP_WAIT(0); else CP_WAIT(1);
        __syncthreads();

        const uint32_t Abase = sb + s * STG_BYTES;
        const uint32_t Bbase = Abase + TILE_BYTES;
#pragma unroll
        for (int ks = 0; ks < 4; ks++) {       // k16 steps within BK=64
            uint32_t af[4][4], bf[4][2];
#pragma unroll
            for (int mi = 0; mi < 4; mi++) {
                uint32_t addr = Abase + (uint32_t)(a_r + mi * 16) * 128
                              + (uint32_t)((((ks << 1) + a_cx) ^ arx) << 4);
                ldsm_x4(af[mi], addr);
            }
#pragma unroll
            for (int g = 0; g < 2; g++) {
                uint32_t tmp[4];
                uint32_t addr = Bbase + (uint32_t)(b_r + g * 16) * 128
                              + (uint32_t)((((ks << 1) + b_cx) ^ brx) << 4);
                ldsm_x4(tmp, addr);
                bf[2 * g][0] = tmp[0]; bf[2 * g][1] = tmp[1];
                bf[2 * g + 1][0] = tmp[2]; bf[2 * g + 1][1] = tmp[3];
            }
#pragma unroll
            for (int mi = 0; mi < 4; mi++)
#pragma unroll
                for (int ni = 0; ni < 4; ni++)
                    mma_f16(acc[mi][ni], af[mi], bf[ni]);
        }

        if (i + 2 < NT) {
            load_stage(sb + ((i + 2) % STAGES) * STG_BYTES,
                       Ag, m0, Bg, n0, (i + 2) * BK, tid);
            CP_COMMIT();
        }
    }
    __syncthreads();   // smem reuse safe for next tile
}

// ---------------------------------------------------------------------------
// prev -> fp16
// ---------------------------------------------------------------------------
__global__ __launch_bounds__(256) void ggru_convert(const float* __restrict__ prev) {
    size_t i = (size_t)blockIdx.x * 256 + threadIdx.x;   // one float4 each
    float4 v = reinterpret_cast<const float4*>(prev)[i];
    __half2 h0 = __floats2half2_rn(v.x, v.y);
    __half2 h1 = __floats2half2_rn(v.z, v.w);
    uint2 u;
    u.x = *reinterpret_cast<uint32_t*>(&h0);
    u.y = *reinterpret_cast<uint32_t*>(&h1);
    reinterpret_cast<uint2*>(g_prevh)[i] = u;
}

// ---------------------------------------------------------------------------
// transpose weights -> fp16 [n][k]; zero work-queue state
// ---------------------------------------------------------------------------
__global__ __launch_bounds__(256) void ggru_transpose(
    const float* __restrict__ Wur, const float* __restrict__ U)
{
    if (blockIdx.x == 0 && blockIdx.y == 0 && blockIdx.z == 0) {
        if (threadIdx.x < MTILES) g_done[threadIdx.x] = 0;
        if (threadIdx.x == 255) g_queue = 0;
    }
    __shared__ float tile[32][33];
    const int mat = blockIdx.z;
    const float* src = mat ? U : (Wur + H);
    const int lds = mat ? H : 2 * H;
    __half* dst = mat ? g_Uh : g_Wh;
    const int kBase = blockIdx.y * 32, nBase = blockIdx.x * 32;
    const int tx = threadIdx.x & 31, ty = threadIdx.x >> 5;

#pragma unroll
    for (int j = 0; j < 4; j++)
        tile[ty + j * 8][tx] = src[(size_t)(kBase + ty + j * 8) * lds + nBase + tx];
    __syncthreads();
#pragma unroll
    for (int j = 0; j < 4; j++)
        dst[(size_t)(nBase + ty + j * 8) * H + kBase + tx] = __float2half(tile[tx][ty + j * 8]);
}

// ---------------------------------------------------------------------------
// Fused persistent kernel: ids 0..1023 GEMM1, 1024..2047 GEMM2 (waits g_done)
// ---------------------------------------------------------------------------
__global__ __launch_bounds__(256, 2) void ggru_fused(
    const float* __restrict__ prev, const float* __restrict__ inp,
    const float* __restrict__ mask, float* __restrict__ out)
{
    extern __shared__ __align__(1024) char smem[];
    __shared__ unsigned s_claim;

    const int tid  = threadIdx.x;
    const int lane = tid & 31, warp = tid >> 5;
    const int wr = warp >> 2, wc = warp & 3;

    for (;;) {
        if (tid == 0) s_claim = atomicAdd(&g_queue, 1u);
        __syncthreads();
        const unsigned c = s_claim;
        __syncthreads();
        if (c >= 2u * TILES_PER_PHASE) return;

        if (c < TILES_PER_PHASE) {
            // ---------------- GEMM1: t = s * sigmoid(prev@Wr + g) ----------
            const int mb = (int)(c >> 3), nb = (int)(c & 7);
            const int m0 = mb * BM, n0 = nb * BN;
            float acc[4][4][4];
            gemm_core(acc, g_prevh, g_Wh, m0, n0, smem);

#pragma unroll
            for (int mi = 0; mi < 4; mi++) {
#pragma unroll
                for (int ni = 0; ni < 4; ni++) {
                    const int r0 = m0 + wr * 64 + mi * 16 + (lane >> 2);
                    const int c0 = n0 + wc * 32 + ni * 8 + (lane & 3) * 2;
#pragma unroll
                    for (int j = 0; j < 2; j++) {
                        const int row = r0 + j * 8;
                        const float* irow = inp + (size_t)row * (3 * H);
                        float2 g = *reinterpret_cast<const float2*>(irow + 2 * H + c0);
                        float2 s = *reinterpret_cast<const float2*>(irow + c0);
                        float x0 = acc[mi][ni][j * 2 + 0] + g.x;
                        float x1 = acc[mi][ni][j * 2 + 1] + g.y;
                        float t0 = s.x * (1.f / (1.f + __expf(-x0)));
                        float t1 = s.y * (1.f / (1.f + __expf(-x1)));
                        __half2 hv = __floats2half2_rn(t0, t1);
                        *reinterpret_cast<uint32_t*>(&g_th[(size_t)row * H + c0]) =
                            *reinterpret_cast<uint32_t*>(&hv);
                    }
                }
            }
            __threadfence();
            __syncthreads();
            if (tid == 0) atomicAdd(&g_done[mb], 1u);
        } else {
            // ---------------- GEMM2: out = prev + m*(tanh(t@U + s)+1) ------
            const unsigned id = c - TILES_PER_PHASE;
            const int mb = (int)(id >> 3), nb = (int)(id & 7);
            const int m0 = mb * BM, n0 = nb * BN;

            if (tid == 0) {
                while (atomicAdd(&g_done[mb], 0u) < (unsigned)NTILES) __nanosleep(64);
            }
            __syncthreads();
            __threadfence();

            float acc[4][4][4];
            gemm_core(acc, g_th, g_Uh, m0, n0, smem);

#pragma unroll
            for (int mi = 0; mi < 4; mi++) {
#pragma unroll
                for (int ni = 0; ni < 4; ni++) {
                    const int r0 = m0 + wr * 64 + mi * 16 + (lane >> 2);
                    const int c0 = n0 + wc * 32 + ni * 8 + (lane & 3) * 2;
#pragma unroll
                    for (int j = 0; j < 2; j++) {
                        const int row = r0 + j * 8;
                        float2 s  = *reinterpret_cast<const float2*>(inp + (size_t)row * (3 * H) + c0);
                        float2 pv = *reinterpret_cast<const float2*>(prev + (size_t)row * H + c0);
                        float mk = mask[row];
                        float n0v = tanhf(acc[mi][ni][j * 2 + 0] + s.x);
                        float n1v = tanhf(acc[mi][ni][j * 2 + 1] + s.y);
                        float2 o;
                        o.x = pv.x + mk * (n0v + 1.f);
                        o.y = pv.y + mk * (n1v + 1.f);
                        *reinterpret_cast<float2*>(out + (size_t)row * H + c0) = o;
                    }
                }
            }
        }
    }
}

// ---------------------------------------------------------------------------
extern "C" void kernel_launch(void* const* d_in, const int* in_sizes, int n_in,
                              void* d_out, int out_size) {
    const float* inp  = (const float*)d_in[0];   // [16384, 3072]
    const float* prev = (const float*)d_in[1];   // [16384, 1024]
    const float* mask = (const float*)d_in[2];   // [16384]
    const float* Wur  = (const float*)d_in[3];   // [1024, 2048]
    const float* U    = (const float*)d_in[4];   // [1024, 1024]
    float* out = (float*)d_out;                  // [16384, 1024]

    cudaFuncSetAttribute(ggru_fused, cudaFuncAttributeMaxDynamicSharedMemorySize, SMEM_TOTAL);

    ggru_convert<<<BATCH * H / (256 * 4), 256>>>(prev);
    ggru_transpose<<<dim3(32, 32, 2), 256>>>(Wur, U);
    ggru_fused<<<304, 256, SMEM_TOTAL>>>(prev, inp, mask, out);
}